// round 3
// baseline (speedup 1.0000x reference)
#include <cuda_runtime.h>
#include <math.h>

#define D      690
#define D2     345      // D/2 (float2 elements per row)
#define R      53
#define NBAGS  25000
#define NTOT   200000

// Scratch for bag attention vectors (allowed: __device__ global array)
__device__ float g_att[(size_t)NBAGS * D];

// ---------------------------------------------------------------------------
// Kernel 1: one block per bag. Online-softmax attention over the bag's rows,
// weighted sum of repre rows kept in registers, result -> g_att.
// ---------------------------------------------------------------------------
__global__ __launch_bounds__(128) void bag_att_kernel(
    const float* __restrict__ repre,
    const float* __restrict__ rel,
    const int* __restrict__ scope,      // int32 (jax x64 disabled)
    const int* __restrict__ labels)     // int32
{
    const int b    = blockIdx.x;
    const int tid  = threadIdx.x;
    const int lane = tid & 31;
    const int wid  = tid >> 5;

    const int s = scope[2 * b];
    const int e = scope[2 * b + 1];
    const int n = e - s;

    __shared__ float l_buf[128];
    __shared__ float red[4];

    const float2* rp = (const float2*)repre;
    const float2* rl = (const float2*)rel;

    float run_m = -INFINITY;
    float run_s = 0.f;
    float2 acc0 = make_float2(0.f, 0.f);
    float2 acc1 = make_float2(0.f, 0.f);
    float2 acc2 = make_float2(0.f, 0.f);
    const int k0 = tid;          // < 345 always
    const int k1 = tid + 128;    // < 345 always
    const int k2 = tid + 256;    // guard < 345

    for (int c0 = 0; c0 < n; c0 += 128) {
        const int cn = min(128, n - c0);

        // ---- pass A: per-row logits, one row per warp (round-robin) ----
        for (int i = wid; i < cn; i += 4) {
            const int row = s + c0 + i;
            const int lab = labels[row];
            const float2* a = rp + (size_t)row * D2;
            const float2* v = rl + (size_t)lab * D2;
            float part = 0.f;
            for (int k = lane; k < D2; k += 32) {
                float2 av = a[k];
                float2 bv = v[k];
                part += av.x * bv.x + av.y * bv.y;
            }
            #pragma unroll
            for (int o = 16; o; o >>= 1)
                part += __shfl_xor_sync(0xffffffffu, part, o);
            if (lane == 0) l_buf[i] = part;
        }
        __syncthreads();

        // ---- chunk max ----
        float lm = -INFINITY;
        for (int t = tid; t < cn; t += 128) lm = fmaxf(lm, l_buf[t]);
        #pragma unroll
        for (int o = 16; o; o >>= 1)
            lm = fmaxf(lm, __shfl_xor_sync(0xffffffffu, lm, o));
        if (lane == 0) red[wid] = lm;
        __syncthreads();
        const float cmax  = fmaxf(fmaxf(red[0], red[1]), fmaxf(red[2], red[3]));
        const float m_new = fmaxf(run_m, cmax);
        __syncthreads();  // red reused below

        // ---- exp + chunk sum (p written back into l_buf) ----
        float ls = 0.f;
        for (int t = tid; t < cn; t += 128) {
            const float p = __expf(l_buf[t] - m_new);
            l_buf[t] = p;
            ls += p;
        }
        #pragma unroll
        for (int o = 16; o; o >>= 1)
            ls += __shfl_xor_sync(0xffffffffu, ls, o);
        if (lane == 0) red[wid] = ls;
        __syncthreads();
        const float csum  = red[0] + red[1] + red[2] + red[3];
        const float scale = __expf(run_m - m_new);  // 0 on first chunk (run_m = -inf)
        run_s = run_s * scale + csum;
        run_m = m_new;
        acc0.x *= scale; acc0.y *= scale;
        acc1.x *= scale; acc1.y *= scale;
        acc2.x *= scale; acc2.y *= scale;

        // ---- pass B: weighted accumulation (rows are cache-hot from pass A) ----
        for (int i = 0; i < cn; ++i) {
            const float p = l_buf[i];
            const float2* a = rp + (size_t)(s + c0 + i) * D2;
            {
                float2 v = a[k0];
                acc0.x += p * v.x; acc0.y += p * v.y;
            }
            {
                float2 v = a[k1];
                acc1.x += p * v.x; acc1.y += p * v.y;
            }
            if (k2 < D2) {
                float2 v = a[k2];
                acc2.x += p * v.x; acc2.y += p * v.y;
            }
        }
        __syncthreads();  // l_buf reused next chunk
    }

    const float inv = (run_s > 0.f) ? (1.f / run_s) : 0.f;
    float2* outp = (float2*)(g_att + (size_t)b * D);
    acc0.x *= inv; acc0.y *= inv; outp[k0] = acc0;
    acc1.x *= inv; acc1.y *= inv; outp[k1] = acc1;
    if (k2 < D2) { acc2.x *= inv; acc2.y *= inv; outp[k2] = acc2; }
}

// ---------------------------------------------------------------------------
// Kernel 2: logits = g_att (25000x690) @ rel^T (690x53) + bias
// Register-tiled fp32 GEMM: block tile 64 m x 56 r, thread tile 4x4, Kc = 32.
// ---------------------------------------------------------------------------
#define MT  64
#define KC  32
#define RT  64   // padded r tile width (zeros beyond R)

__global__ __launch_bounds__(256) void logits_gemm_kernel(
    const float* __restrict__ rel,
    const float* __restrict__ bias,
    float* __restrict__ out)
{
    __shared__ __align__(16) float a_s[KC][68];  // [k][m], stride 68 (16B-aligned rows)
    __shared__ __align__(16) float b_s[KC][RT];  // [k][r], 64 floats = 16B-aligned rows

    const int m0   = blockIdx.x * MT;
    const int tid  = threadIdx.x;
    const int lane = tid & 31;
    const int wid  = tid >> 5;
    const int tx   = tid & 15;   // r group: r = tx*4 + j (valid r < 53)
    const int ty   = tid >> 4;   // m group: m = m0 + ty*4 + i

    float acc[4][4] = {};

    for (int kc = 0; kc < D; kc += KC) {
        // load A tile: one k-slice per lane, warp walks m rows
        for (int mi = wid; mi < MT; mi += 8) {
            const int m = m0 + mi;
            const int k = kc + lane;
            float v = 0.f;
            if (m < NBAGS && k < D) v = g_att[(size_t)m * D + k];
            a_s[lane][mi] = v;
        }
        // load B tile (zero-padded to RT columns)
        for (int ri = wid; ri < RT; ri += 8) {
            const int k = kc + lane;
            float v = 0.f;
            if (ri < R && k < D) v = rel[(size_t)ri * D + k];
            b_s[lane][ri] = v;
        }
        __syncthreads();

        #pragma unroll
        for (int k = 0; k < KC; ++k) {
            const float4 af = *(const float4*)&a_s[k][ty * 4];
            const float4 bf = *(const float4*)&b_s[k][tx * 4];
            const float a[4] = {af.x, af.y, af.z, af.w};
            const float b[4] = {bf.x, bf.y, bf.z, bf.w};
            #pragma unroll
            for (int i = 0; i < 4; ++i)
                #pragma unroll
                for (int j = 0; j < 4; ++j)
                    acc[i][j] += a[i] * b[j];
        }
        __syncthreads();
    }

    #pragma unroll
    for (int i = 0; i < 4; ++i) {
        const int m = m0 + ty * 4 + i;
        if (m >= NBAGS) break;
        #pragma unroll
        for (int j = 0; j < 4; ++j) {
            const int r = tx * 4 + j;
            if (r < R) out[(size_t)m * R + r] = acc[i][j] + bias[r];
        }
    }
}

// ---------------------------------------------------------------------------
extern "C" void kernel_launch(void* const* d_in, const int* in_sizes, int n_in,
                              void* d_out, int out_size)
{
    const float* repre  = (const float*)d_in[0];   // (N, D) f32
    const float* rel    = (const float*)d_in[1];   // (R, D) f32
    const float* bias   = (const float*)d_in[2];   // (R,)   f32
    const int*   scope  = (const int*)d_in[3];     // (NBAGS, 2) i32
    const int*   labels = (const int*)d_in[4];     // (N,)   i32
    float* out = (float*)d_out;                    // (NBAGS, R) f32

    bag_att_kernel<<<NBAGS, 128>>>(repre, rel, scope, labels);

    const int gblocks = (NBAGS + MT - 1) / MT;
    logits_gemm_kernel<<<gblocks, 256>>>(rel, bias, out);
}

// round 4
// speedup vs baseline: 1.0852x; 1.0852x over previous
#include <cuda_runtime.h>
#include <math.h>

#define D      690
#define D2     345      // D/2 (float2 per row)
#define R      53
#define NBAGS  25000
#define NTOT   200000

// Scratch for bag attention vectors (allowed: __device__ global array)
__device__ __align__(16) float g_att[(size_t)NBAGS * D];

// ---------------------------------------------------------------------------
// Kernel 1: ONE WARP PER BAG, single pass.
// Per row: dot(repre_row, rel[label]) with row kept in registers; online
// softmax rescale folds the row into the accumulator immediately.
// repre is read from DRAM exactly once. No smem, no __syncthreads.
// ---------------------------------------------------------------------------
__global__ __launch_bounds__(256) void bag_att_kernel(
    const float* __restrict__ repre,
    const float* __restrict__ rel,
    const int* __restrict__ scope,     // int32
    const int* __restrict__ labels)    // int32
{
    const int w = (blockIdx.x * blockDim.x + threadIdx.x) >> 5;
    if (w >= NBAGS) return;
    const int lane = threadIdx.x & 31;

    const int s = scope[2 * w];
    const int e = scope[2 * w + 1];

    const float2* rp = (const float2*)repre;
    const float2* rl = (const float2*)rel;

    // lane handles k = lane + 32*j, j = 0..10 (j=10 only if lane < 25)
    float2 aR[11];
    float2 acc[11];
    #pragma unroll
    for (int j = 0; j < 11; ++j) acc[j] = make_float2(0.f, 0.f);
    const bool tail = (lane < (D2 - 320));  // 345 - 320 = 25

    float run_m = -INFINITY;
    float run_s = 0.f;

    for (int row = s; row < e; ++row) {
        const int lab = labels[row];                 // uniform -> broadcast
        const float2* a = rp + (size_t)row * D2;
        const float2* v = rl + (size_t)lab * D2;

        float part = 0.f;
        #pragma unroll
        for (int j = 0; j < 10; ++j) {
            const int k = lane + 32 * j;
            aR[j] = a[k];
            const float2 vv = v[k];
            part = fmaf(aR[j].x, vv.x, part);
            part = fmaf(aR[j].y, vv.y, part);
        }
        if (tail) {
            const int k = lane + 320;
            aR[10] = a[k];
            const float2 vv = v[k];
            part = fmaf(aR[10].x, vv.x, part);
            part = fmaf(aR[10].y, vv.y, part);
        } else {
            aR[10] = make_float2(0.f, 0.f);
        }

        #pragma unroll
        for (int o = 16; o; o >>= 1)
            part += __shfl_xor_sync(0xffffffffu, part, o);
        // part == full logit l, identical on all lanes

        const float m_new = fmaxf(run_m, part);
        const float sc    = __expf(run_m - m_new);   // 0 on first row
        const float p     = __expf(part - m_new);
        run_s = run_s * sc + p;
        run_m = m_new;
        #pragma unroll
        for (int j = 0; j < 11; ++j) {
            acc[j].x = acc[j].x * sc + p * aR[j].x;
            acc[j].y = acc[j].y * sc + p * aR[j].y;
        }
    }

    const float inv = 1.f / run_s;
    float2* outp = (float2*)(g_att + (size_t)w * D);
    #pragma unroll
    for (int j = 0; j < 10; ++j) {
        float2 o = acc[j];
        o.x *= inv; o.y *= inv;
        outp[lane + 32 * j] = o;
    }
    if (tail) {
        float2 o = acc[10];
        o.x *= inv; o.y *= inv;
        outp[lane + 320] = o;
    }
}

// ---------------------------------------------------------------------------
// Kernel 2: logits = g_att (25000x690) @ rel^T (690x53) + bias
// Block tile 128m x 56r, thread tile 8m x 4r, Kc=32.
// Inner product uses packed fma.rn.f32x2 (FFMA2): m-pairs come packed for
// free from the A float4; b is splatted via mov.b64 (ALU pipe).
// ---------------------------------------------------------------------------
#define GM  128
#define GKC 32

#define PACK_SPLAT(o, f) \
    asm("mov.b64 %0, {%1, %1};" : "=l"(o) : "r"(__float_as_uint(f)))
#define FMA2(d, a, b) \
    asm("fma.rn.f32x2 %0, %1, %2, %0;" : "+l"(d) : "l"(a), "l"(b))

__global__ __launch_bounds__(256) void logits_gemm_kernel(
    const float* __restrict__ rel,
    const float* __restrict__ bias,
    float* __restrict__ out)
{
    __shared__ __align__(16) float a_s[GKC][GM];   // 16 KB  [k][m]
    __shared__ __align__(16) float b_s[GKC][64];   //  8 KB  [k][r], zero-padded

    const int tid = threadIdx.x;
    const int tx  = tid & 15;    // r group: r = tx*4 + j
    const int ty  = tid >> 4;    // m group: m = m0 + ty*8 + i
    const int m0  = blockIdx.x * GM;

    // A-tile loader mapping: 256 threads cover 128 m x 32 k
    const int lm = tid & 127;           // m within tile
    const int kh = (tid >> 7) * 16;     // k half: 0 or 16 (uniform per warp)
    const int gm = m0 + lm;
    const bool mok = (gm < NBAGS);
    const float* asrc = g_att + (size_t)gm * D;

    unsigned long long acc2[4][4];      // [m-pair][r], each = 2 packed f32
    #pragma unroll
    for (int i = 0; i < 4; ++i)
        #pragma unroll
        for (int j = 0; j < 4; ++j) acc2[i][j] = 0ull;

    for (int kc = 0; kc < D; kc += GKC) {
        // ---- A tile: thread loads 16 consecutive k of its row (float2 x8) ----
        #pragma unroll
        for (int j = 0; j < 8; ++j) {
            const int k = kc + kh + 2 * j;
            float2 v = make_float2(0.f, 0.f);
            if (mok && k < D) v = *(const float2*)(asrc + k);
            a_s[kh + 2 * j][lm]     = v.x;
            a_s[kh + 2 * j + 1][lm] = v.y;
        }
        // ---- B tile (zero-padded r >= R) ----
        #pragma unroll
        for (int it = 0; it < (GKC * 64) / 256; ++it) {
            const int idx = tid + it * 256;
            const int k = idx >> 6, r = idx & 63;
            float v = 0.f;
            if (r < R && kc + k < D) v = rel[(size_t)r * D + kc + k];
            b_s[k][r] = v;
        }
        __syncthreads();

        #pragma unroll
        for (int k = 0; k < GKC; ++k) {
            const ulonglong2 a01 = *(const ulonglong2*)&a_s[k][ty * 8];
            const ulonglong2 a23 = *(const ulonglong2*)&a_s[k][ty * 8 + 4];
            const float4 bf = *(const float4*)&b_s[k][tx * 4];
            unsigned long long ap[4] = {a01.x, a01.y, a23.x, a23.y};
            unsigned long long bp[4];
            PACK_SPLAT(bp[0], bf.x);
            PACK_SPLAT(bp[1], bf.y);
            PACK_SPLAT(bp[2], bf.z);
            PACK_SPLAT(bp[3], bf.w);
            #pragma unroll
            for (int i = 0; i < 4; ++i)
                #pragma unroll
                for (int j = 0; j < 4; ++j)
                    FMA2(acc2[i][j], ap[i], bp[j]);
        }
        __syncthreads();
    }

    // ---- epilogue ----
    #pragma unroll
    for (int j = 0; j < 4; ++j) {
        const int r = tx * 4 + j;
        if (r >= R) continue;
        const float bi = bias[r];
        #pragma unroll
        for (int i = 0; i < 4; ++i) {
            unsigned int lo, hi;
            asm("mov.b64 {%0, %1}, %2;" : "=r"(lo), "=r"(hi) : "l"(acc2[i][j]));
            const int m = m0 + ty * 8 + 2 * i;
            if (m < NBAGS)     out[(size_t)m * R + r]       = __uint_as_float(lo) + bi;
            if (m + 1 < NBAGS) out[(size_t)(m + 1) * R + r] = __uint_as_float(hi) + bi;
        }
    }
}

// ---------------------------------------------------------------------------
extern "C" void kernel_launch(void* const* d_in, const int* in_sizes, int n_in,
                              void* d_out, int out_size)
{
    const float* repre  = (const float*)d_in[0];   // (N, D) f32
    const float* rel    = (const float*)d_in[1];   // (R, D) f32
    const float* bias   = (const float*)d_in[2];   // (R,)   f32
    const int*   scope  = (const int*)d_in[3];     // (NBAGS, 2) i32
    const int*   labels = (const int*)d_in[4];     // (N,)   i32
    float* out = (float*)d_out;                    // (NBAGS, R) f32

    const int warps_needed = NBAGS;                           // 1 warp / bag
    const int blocks1 = (warps_needed * 32 + 255) / 256;      // 3125
    bag_att_kernel<<<blocks1, 256>>>(repre, rel, scope, labels);

    const int blocks2 = (NBAGS + GM - 1) / GM;                // 196
    logits_gemm_kernel<<<blocks2, 256>>>(rel, bias, out);
}